// round 12
// baseline (speedup 1.0000x reference)
#include <cuda_runtime.h>
#include <cuda_fp16.h>
#include <cstdint>

// Problem shape (fixed by the dataset)
#define BATCH 8
#define LSEQ  2048
#define DDIM  1024
#define TAW_INV 50.0f

// fp8 e4m3 input scale: x*8 (max |x|~5.2 -> 42 << 448). Scores scaled by 64.
#define FP8_SCALE 8.0f

// Scratch (static __device__ arrays — allocation-free rule)
__device__ uint8_t g_Q8[(size_t)BATCH * LSEQ * DDIM];         // 16.8 MB (e4m3)
__device__ uint8_t g_M8[(size_t)BATCH * LSEQ * DDIM];         // 16.8 MB (e4m3)
__device__ __half  g_S [(size_t)BATCH * LSEQ * LSEQ];         // 67 MB (dots x64)
__device__ __half  g_bmax[(size_t)BATCH * LSEQ * 64];         // per-row 32-col block max (2 MB)

// ---------------------------------------------------------------------------
// Helpers
// ---------------------------------------------------------------------------
__device__ __forceinline__ uint32_t smem_u32(const void* p) {
    uint32_t a;
    asm("{ .reg .u64 t; cvta.to.shared.u64 t, %1; cvt.u32.u64 %0, t; }"
        : "=r"(a) : "l"(p));
    return a;
}

__device__ __forceinline__ void cp_async16(uint32_t saddr, const void* gptr) {
    asm volatile("cp.async.cg.shared.global [%0], [%1], 16;\n" :: "r"(saddr), "l"(gptr));
}

#define LDSM_X4(r, addr) \
    asm volatile("ldmatrix.sync.aligned.m8n8.x4.shared.b16 {%0,%1,%2,%3}, [%4];" \
        : "=r"((r)[0]), "=r"((r)[1]), "=r"((r)[2]), "=r"((r)[3]) : "r"(addr))

// fp8 e4m3 MMA, f32 accumulators (m16n8k32)
#define MMAF8(d, a, b)                                                        \
    asm volatile(                                                             \
        "mma.sync.aligned.m16n8k32.row.col.f32.e4m3.e4m3.f32 "                \
        "{%0,%1,%2,%3}, {%4,%5,%6,%7}, {%8,%9}, {%0,%1,%2,%3};\n"             \
        : "+f"((d)[0]), "+f"((d)[1]), "+f"((d)[2]), "+f"((d)[3])              \
        : "r"((a)[0]), "r"((a)[1]), "r"((a)[2]), "r"((a)[3]),                 \
          "r"((b)[0]), "r"((b)[1]))

// pack two floats into e4m3x2 (a -> high byte, b -> low byte)
__device__ __forceinline__ uint16_t cvt2_e4m3(float hi, float lo) {
    uint16_t r;
    asm("cvt.rn.satfinite.e4m3x2.f32 %0, %1, %2;" : "=h"(r) : "f"(hi), "f"(lo));
    return r;
}

// ---------------------------------------------------------------------------
// Kernel 1: fp32 -> e4m3 (x8) conversion of query and memory
// ---------------------------------------------------------------------------
__global__ void convert_kernel(const float* __restrict__ q, const float* __restrict__ m) {
    size_t i = (size_t)blockIdx.x * blockDim.x + threadIdx.x;   // 8-float groups
    size_t n8 = (size_t)BATCH * LSEQ * DDIM / 8;
    if (i >= n8) return;
    const float4* q4 = (const float4*)q;
    const float4* m4 = (const float4*)m;
    float4 a0 = q4[2*i], a1 = q4[2*i+1];
    float4 b0 = m4[2*i], b1 = m4[2*i+1];
    uint32_t qa = (uint32_t)cvt2_e4m3(a0.y * FP8_SCALE, a0.x * FP8_SCALE)
                | ((uint32_t)cvt2_e4m3(a0.w * FP8_SCALE, a0.z * FP8_SCALE) << 16);
    uint32_t qb = (uint32_t)cvt2_e4m3(a1.y * FP8_SCALE, a1.x * FP8_SCALE)
                | ((uint32_t)cvt2_e4m3(a1.w * FP8_SCALE, a1.z * FP8_SCALE) << 16);
    uint32_t ma = (uint32_t)cvt2_e4m3(b0.y * FP8_SCALE, b0.x * FP8_SCALE)
                | ((uint32_t)cvt2_e4m3(b0.w * FP8_SCALE, b0.z * FP8_SCALE) << 16);
    uint32_t mb = (uint32_t)cvt2_e4m3(b1.y * FP8_SCALE, b1.x * FP8_SCALE)
                | ((uint32_t)cvt2_e4m3(b1.w * FP8_SCALE, b1.z * FP8_SCALE) << 16);
    ((uint2*)g_Q8)[i] = make_uint2(qa, qb);
    ((uint2*)g_M8)[i] = make_uint2(ma, mb);
}

// ---------------------------------------------------------------------------
// Kernel 2: fp8 e4m3 mma.sync GEMM (f32 acc), 128x128 tile, BK=64 bytes,
// 4-stage cp.async, ldmatrix (validated R6 int8 addressing), 2 CTAs/SM.
// Stores scaled dots (x64) fp16 + per-(row, 32col-block) max (no atomics).
// ---------------------------------------------------------------------------
#define BM 128
#define BN 128
#define BKB 64                             // k-bytes per stage
#define PITCH_B 80                         // bytes per smem row (64 used + 16 pad)
#define STG_SZ  (BM * PITCH_B)             // 10240 B per operand stage
#define NSTG 4
#define NKB (DDIM / BKB)                   // 16
#define QK_DSMEM (2 * NSTG * STG_SZ)       // 81920 B

__global__ __launch_bounds__(256, 2) void qk_gemm_kernel() {
    extern __shared__ __align__(16) char dsm[];
    const uint32_t sb = smem_u32(dsm);

    const int tid   = threadIdx.x;
    const int lane  = tid & 31;
    const int warp  = tid >> 5;
    const int warpM = warp >> 2;           // 0..1  -> 64-row stripe
    const int warpN = warp & 3;            // 0..3  -> 32-col stripe
    const int g     = lane >> 2;
    const int t     = lane & 3;

    const int b     = blockIdx.z;
    const int mBase = blockIdx.y * BM;
    const int nBase = blockIdx.x * BN;
    const uint8_t* Qb = g_Q8 + (size_t)b * LSEQ * DDIM;
    const uint8_t* Mb = g_M8 + (size_t)b * LSEQ * DDIM;

    uint32_t aS[NSTG], bS[NSTG];
    #pragma unroll
    for (int s = 0; s < NSTG; s++) {
        aS[s] = sb + s * STG_SZ;
        bS[s] = sb + NSTG * STG_SZ + s * STG_SZ;
    }

    // ldmatrix per-thread addressing (validated in R6 on int8)
    const int rowA  = warpM * 64 + (lane & 7) + ((lane >> 3) & 1) * 8;
    const int colAb = ((lane >> 4) & 1) * 16;        // byte offset
    const int rowB  = warpN * 32 + (lane & 7) + ((lane >> 4) & 1) * 8;
    const int colBb = ((lane >> 3) & 1) * 16;

    float acc[4][4][4];
    #pragma unroll
    for (int i = 0; i < 4; i++)
        #pragma unroll
        for (int j = 0; j < 4; j++)
            #pragma unroll
            for (int r = 0; r < 4; r++) acc[i][j][r] = 0.f;

    auto load_stage = [&](int s, int kb) {
        int k0 = kb * BKB;                           // byte offset along k
        #pragma unroll
        for (int i = 0; i < 2; i++) {                // 512 chunks per operand
            int j = tid + i * 256;
            int row = j >> 2;
            int c16 = (j & 3) * 16;
            cp_async16(aS[s] + row * PITCH_B + c16,
                       Qb + (size_t)(mBase + row) * DDIM + k0 + c16);
            cp_async16(bS[s] + row * PITCH_B + c16,
                       Mb + (size_t)(nBase + row) * DDIM + k0 + c16);
        }
        asm volatile("cp.async.commit_group;\n");
    };

    // prologue: 3 stages in flight
    load_stage(0, 0);
    load_stage(1, 1);
    load_stage(2, 2);

    for (int kb = 0; kb < NKB; kb++) {
        int s = kb & (NSTG - 1);
        if (kb < NKB - 2)       asm volatile("cp.async.wait_group 2;\n");
        else if (kb == NKB - 2) asm volatile("cp.async.wait_group 1;\n");
        else                    asm volatile("cp.async.wait_group 0;\n");
        __syncthreads();

        if (kb + 3 < NKB) load_stage((kb + 3) & (NSTG - 1), kb + 3);

        uint32_t aBase = aS[s] + rowA * PITCH_B + colAb;
        uint32_t bBase = bS[s] + rowB * PITCH_B + colBb;
        #pragma unroll
        for (int ks = 0; ks < 2; ks++) {             // two k32 slabs per 64B row
            uint32_t af[4][4], bf[2][4];
            #pragma unroll
            for (int mt = 0; mt < 4; mt++)
                LDSM_X4(af[mt], aBase + mt * (16 * PITCH_B) + ks * 32);
            #pragma unroll
            for (int n2 = 0; n2 < 2; n2++)
                LDSM_X4(bf[n2], bBase + n2 * (16 * PITCH_B) + ks * 32);
            #pragma unroll
            for (int mt = 0; mt < 4; mt++)
                #pragma unroll
                for (int nt = 0; nt < 4; nt++)
                    MMAF8(acc[mt][nt], af[mt], &bf[nt >> 1][(nt & 1) * 2]);
        }
    }

    // Epilogue: store scaled dots fp16 + per-(row, 32col-block) max plain stores
    __half* Srow = g_S + (size_t)b * LSEQ * LSEQ;
    const int ntile = (nBase >> 5) + warpN;          // 0..63, unique per warp
    #pragma unroll
    for (int mt = 0; mt < 4; mt++) {
        float vmax0 = -1e30f, vmax1 = -1e30f;
        #pragma unroll
        for (int nt = 0; nt < 4; nt++) {
            int row = mBase + warpM * 64 + mt * 16 + g;
            int col = nBase + warpN * 32 + nt * 8 + 2 * t;
            *(half2*)(Srow + (size_t)(row    ) * LSEQ + col) =
                __floats2half2_rn(acc[mt][nt][0], acc[mt][nt][1]);
            *(half2*)(Srow + (size_t)(row + 8) * LSEQ + col) =
                __floats2half2_rn(acc[mt][nt][2], acc[mt][nt][3]);
            vmax0 = fmaxf(vmax0, fmaxf(acc[mt][nt][0], acc[mt][nt][1]));
            vmax1 = fmaxf(vmax1, fmaxf(acc[mt][nt][2], acc[mt][nt][3]));
        }
        #pragma unroll
        for (int o = 1; o <= 2; o <<= 1) {           // reduce across t-threads
            vmax0 = fmaxf(vmax0, __shfl_xor_sync(0xffffffffu, vmax0, o));
            vmax1 = fmaxf(vmax1, __shfl_xor_sync(0xffffffffu, vmax1, o));
        }
        if (t == 0) {
            int row = mBase + warpM * 64 + mt * 16 + g;
            g_bmax[((size_t)b * LSEQ + row    ) * 64 + ntile] = __float2half(vmax0);
            g_bmax[((size_t)b * LSEQ + row + 8) * 64 + ntile] = __float2half(vmax1);
        }
    }
}

// ---------------------------------------------------------------------------
// Kernel 3: per-row refine. Scores/bmax are scaled x64; margin 10 raw dots
// = 640 scaled (covers e4m3 error sigma~1.6 at 6 sigma). Exact fp32 dots +
// exact softmax for candidates; nc==1 fast path (exact row copy).
// ---------------------------------------------------------------------------
#define CAP 64
#define MARGIN_SC 640.0f

__global__ __launch_bounds__(256) void refine_kernel(const float* __restrict__ Q,
                                                     const float* __restrict__ Mem,
                                                     float* __restrict__ Out) {
    const int b = blockIdx.y, q = blockIdx.x, tid = threadIdx.x;
    const int lane = tid & 31, warp = tid >> 5;
    const __half* srow = g_S + ((size_t)b * LSEQ + q) * LSEQ;

    __shared__ int   s_cnt;
    __shared__ int   s_nblk;
    __shared__ float s_thr;
    __shared__ int   s_blk[64];
    __shared__ int   s_idx[CAP];
    __shared__ float s_dot[CAP];
    __shared__ float s_w[CAP];

    // 1) block maxes -> row max, threshold, flagged 32-col blocks (warp 0)
    if (warp == 0) {
        __half2 h = ((const __half2*)(g_bmax + ((size_t)b * LSEQ + q) * 64))[lane];
        float v0 = __low2float(h), v1 = __high2float(h);
        float mx = fmaxf(v0, v1);
        #pragma unroll
        for (int o = 16; o; o >>= 1) mx = fmaxf(mx, __shfl_xor_sync(0xffffffffu, mx, o));
        float thr = mx - MARGIN_SC;
        if (lane == 0) { s_thr = thr; s_cnt = 0; s_nblk = 0; }
        __syncwarp();
        if (v0 >= thr) s_blk[atomicAdd(&s_nblk, 1)] = 2 * lane;
        if (v1 >= thr) s_blk[atomicAdd(&s_nblk, 1)] = 2 * lane + 1;
    }
    __syncthreads();

    // 2) candidate scan over flagged 32-score blocks only
    {
        float thr = s_thr;
        int nblk = s_nblk;
        for (int bi = warp; bi < nblk; bi += 8) {
            int k = s_blk[bi] * 32 + lane;
            if (__half2float(srow[k]) >= thr) {
                int p = atomicAdd(&s_cnt, 1);
                if (p < CAP) s_idx[p] = k;
            }
        }
    }
    __syncthreads();
    int nc = min(s_cnt, CAP);

    // 3) fast path: single candidate -> output = that memory row exactly
    if (nc == 1) {
        const float4* src = (const float4*)(Mem + ((size_t)b * LSEQ + s_idx[0]) * DDIM);
        float4* dst = (float4*)(Out + ((size_t)b * LSEQ + q) * DDIM);
        dst[tid] = src[tid];                 // 256 threads x float4 = 1024
        return;
    }

    if (tid == 0) {                          // sort for determinism
        for (int i = 1; i < nc; i++) {
            int v = s_idx[i], j = i - 1;
            while (j >= 0 && s_idx[j] > v) { s_idx[j + 1] = s_idx[j]; j--; }
            s_idx[j + 1] = v;
        }
    }
    __syncthreads();

    // 4) exact fp32 dots, one warp per candidate
    const float* qrow = Q + ((size_t)b * LSEQ + q) * DDIM;
    for (int j = warp; j < nc; j += 8) {
        const float* mrow = Mem + ((size_t)b * LSEQ + s_idx[j]) * DDIM;
        float p = 0.f;
        #pragma unroll 4
        for (int d = lane; d < DDIM; d += 32) p += qrow[d] * mrow[d];
        #pragma unroll
        for (int o = 16; o; o >>= 1) p += __shfl_xor_sync(0xffffffffu, p, o);
        if (lane == 0) s_dot[j] = p;
    }
    __syncthreads();

    // 5) exact softmax over candidates
    if (tid == 0) {
        float dm = -1e30f;
        for (int j = 0; j < nc; j++) dm = fmaxf(dm, s_dot[j]);
        float sum = 0.f;
        for (int j = 0; j < nc; j++) {
            float w = expf((s_dot[j] - dm) * TAW_INV);
            s_w[j] = w; sum += w;
        }
        float inv = 1.0f / sum;
        for (int j = 0; j < nc; j++) s_w[j] *= inv;
    }
    __syncthreads();

    // 6) output mixture (float4 vectorized)
    const float4* M4 = (const float4*)Mem;
    float4* dst = (float4*)(Out + ((size_t)b * LSEQ + q) * DDIM);
    float4 a = make_float4(0.f, 0.f, 0.f, 0.f);
    for (int j = 0; j < nc; j++) {
        float w = s_w[j];
        float4 v = M4[(((size_t)b * LSEQ + s_idx[j]) * DDIM >> 2) + tid];
        a.x += w * v.x; a.y += w * v.y; a.z += w * v.z; a.w += w * v.w;
    }
    dst[tid] = a;
}

// ---------------------------------------------------------------------------
extern "C" void kernel_launch(void* const* d_in, const int* in_sizes, int n_in,
                              void* d_out, int out_size) {
    const float* q = (const float*)d_in[0];
    const float* m = (const float*)d_in[1];
    float* out = (float*)d_out;

    // Host-side attribute set (not a stream op -> capture-safe)
    cudaFuncSetAttribute(qk_gemm_kernel,
                         cudaFuncAttributeMaxDynamicSharedMemorySize, QK_DSMEM);

    size_t n8 = (size_t)BATCH * LSEQ * DDIM / 8;   // 2,097,152
    convert_kernel<<<(unsigned)((n8 + 255) / 256), 256>>>(q, m);

    dim3 gg(LSEQ / BN, LSEQ / BM, BATCH);          // 16 x 16 x 8
    qk_gemm_kernel<<<gg, 256, QK_DSMEM>>>();

    dim3 rg(LSEQ, BATCH);
    refine_kernel<<<rg, 256>>>(q, m, out);
}

// round 13
// speedup vs baseline: 1.0952x; 1.0952x over previous
#include <cuda_runtime.h>
#include <cuda_fp16.h>
#include <cstdint>

// Problem shape (fixed by the dataset)
#define BATCH 8
#define LSEQ  2048
#define DDIM  1024
#define TAW_INV 50.0f

// Scratch (static __device__ arrays — allocation-free rule)
__device__ __half g_Qh[(size_t)BATCH * LSEQ * DDIM];          // 33.5 MB
__device__ __half g_Mh[(size_t)BATCH * LSEQ * DDIM];          // 33.5 MB
__device__ __half g_S [(size_t)BATCH * LSEQ * LSEQ];          // 67 MB (approx dots)
__device__ __half g_bmax[(size_t)BATCH * LSEQ * 32];          // per-row 64-col block max

// Scheduling state (reset by init_kernel every invocation)
__device__ int g_ticket;
__device__ int g_conv_prog[BATCH];
__device__ int g_gemm_prog[BATCH];

// Ticket layout: per batch b: 512 conv tickets then 128 gemm tickets (segment
// 640); after all 8 segments, 512 refine tickets (64 per batch, 32 rows each).
#define CONV_PER_B 512
#define GEMM_PER_B 128
#define SEG        (CONV_PER_B + GEMM_PER_B)      // 640
#define NCG        (BATCH * SEG)                  // 5120
#define REF_PER_B  64
#define NTICK      (NCG + BATCH * REF_PER_B)      // 5632
#define NCTA       296

// ---------------------------------------------------------------------------
// Helpers
// ---------------------------------------------------------------------------
__device__ __forceinline__ uint32_t smem_u32(const void* p) {
    uint32_t a;
    asm("{ .reg .u64 t; cvta.to.shared.u64 t, %1; cvt.u32.u64 %0, t; }"
        : "=r"(a) : "l"(p));
    return a;
}

__device__ __forceinline__ void cp_async16(uint32_t saddr, const void* gptr) {
    asm volatile("cp.async.cg.shared.global [%0], [%1], 16;\n" :: "r"(saddr), "l"(gptr));
}

#define LDSM_X4(r, addr) \
    asm volatile("ldmatrix.sync.aligned.m8n8.x4.shared.b16 {%0,%1,%2,%3}, [%4];" \
        : "=r"((r)[0]), "=r"((r)[1]), "=r"((r)[2]), "=r"((r)[3]) : "r"(addr))

#define MMAF16(d, a, b)                                                       \
    asm volatile(                                                             \
        "mma.sync.aligned.m16n8k16.row.col.f16.f16.f16.f16 "                  \
        "{%0,%1}, {%2,%3,%4,%5}, {%6,%7}, {%0,%1};\n"                         \
        : "+r"((d)[0]), "+r"((d)[1])                                          \
        : "r"((a)[0]), "r"((a)[1]), "r"((a)[2]), "r"((a)[3]),                 \
          "r"((b)[0]), "r"((b)[1]))

__device__ __forceinline__ float ldcg_half(const __half* p) {
    unsigned short u;
    asm volatile("ld.global.cg.u16 %0, [%1];" : "=h"(u) : "l"(p));
    __half h; *(unsigned short*)&h = u;
    return __half2float(h);
}
__device__ __forceinline__ __half2 ldcg_half2(const __half2* p) {
    unsigned int u;
    asm volatile("ld.global.cg.u32 %0, [%1];" : "=r"(u) : "l"(p));
    return *(__half2*)&u;
}

// bounded acquire-spin on a progress counter (never hangs the container)
__device__ __forceinline__ void cta_wait(int* ctr, int target, int tid) {
    if (tid == 0) {
        int it = 0;
        while (atomicAdd(ctr, 0) < target && ++it < (1 << 22)) {}
    }
    __syncthreads();
}

// ---------------------------------------------------------------------------
// GEMM config (identical to validated R10 kernel)
// ---------------------------------------------------------------------------
#define BM 128
#define BN 256
#define BK 32
#define PITCH_B 80
#define A_STG (BM * PITCH_B)               // 10240
#define B_STG (BN * PITCH_B)               // 20480
#define NSTG 3
#define NKB (DDIM / BK)                    // 32
#define QK_DSMEM (NSTG * (A_STG + B_STG))  // 92160 B

// ---------------------------------------------------------------------------
// Phase bodies
// ---------------------------------------------------------------------------
__device__ __forceinline__ void conv_ticket(int t, const float* __restrict__ q,
                                            const float* __restrict__ m, int tid) {
    int b = t / SEG, seg = t % SEG;        // seg < CONV_PER_B guaranteed by caller
    size_t base = (size_t)b * (LSEQ * DDIM / 4) + (size_t)seg * 1024;
    const float4* q4 = (const float4*)q;
    const float4* m4 = (const float4*)m;
    __half2* Q2 = (__half2*)g_Qh;
    __half2* M2 = (__half2*)g_Mh;
    #pragma unroll
    for (int k = 0; k < 4; k++) {
        size_t i = base + tid + k * 256;
        float4 vq = q4[i];
        float4 vm = m4[i];
        Q2[2*i]   = __floats2half2_rn(vq.x, vq.y);
        Q2[2*i+1] = __floats2half2_rn(vq.z, vq.w);
        M2[2*i]   = __floats2half2_rn(vm.x, vm.y);
        M2[2*i+1] = __floats2half2_rn(vm.z, vm.w);
    }
    __threadfence();
    __syncthreads();
    if (tid == 0) atomicAdd(&g_conv_prog[b], 1);
}

__device__ __forceinline__ void gemm_ticket(int b, int tb, char* dsm, int tid) {
    cta_wait(&g_conv_prog[b], CONV_PER_B, tid);

    const uint32_t sb = smem_u32(dsm);
    const int lane  = tid & 31;
    const int warp  = tid >> 5;
    const int warpM = warp & 1;
    const int warpN = warp >> 1;
    const int g     = lane >> 2;
    const int t     = lane & 3;

    const int mBase = (tb >> 3) * BM;      // 16 m-tiles
    const int nBase = (tb & 7) * BN;       // 8 n-tiles
    const __half* Qb = g_Qh + (size_t)b * LSEQ * DDIM;
    const __half* Mb = g_Mh + (size_t)b * LSEQ * DDIM;

    uint32_t aS[NSTG], bS[NSTG];
    #pragma unroll
    for (int s = 0; s < NSTG; s++) {
        aS[s] = sb + s * (A_STG + B_STG);
        bS[s] = aS[s] + A_STG;
    }

    const int rowA = warpM * 64 + (lane & 7) + ((lane >> 3) & 1) * 8;
    const int colA = ((lane >> 4) & 1) * 8;
    const int rowB = warpN * 64 + (lane & 7) + ((lane >> 4) & 1) * 8;
    const int colB = ((lane >> 3) & 1) * 8;

    uint32_t acc[4][8][2];
    #pragma unroll
    for (int i = 0; i < 4; i++)
        #pragma unroll
        for (int j = 0; j < 8; j++) { acc[i][j][0] = 0u; acc[i][j][1] = 0u; }

    auto load_stage = [&](int s, int kb) {
        int k0 = kb * BK;
        #pragma unroll
        for (int i = 0; i < 2; i++) {
            int j = tid + i * 256;
            int row = j >> 2;
            int c16 = (j & 3) * 16;
            cp_async16(aS[s] + row * PITCH_B + c16,
                       Qb + (size_t)(mBase + row) * DDIM + k0 + c16 / 2);
        }
        #pragma unroll
        for (int i = 0; i < 4; i++) {
            int j = tid + i * 256;
            int row = j >> 2;
            int c16 = (j & 3) * 16;
            cp_async16(bS[s] + row * PITCH_B + c16,
                       Mb + (size_t)(nBase + row) * DDIM + k0 + c16 / 2);
        }
        asm volatile("cp.async.commit_group;\n");
    };

    load_stage(0, 0);
    load_stage(1, 1);

    for (int kb = 0; kb < NKB; kb++) {
        int s = kb % NSTG;
        if (kb + 2 < NKB) asm volatile("cp.async.wait_group 1;\n");
        else              asm volatile("cp.async.wait_group 0;\n");
        __syncthreads();

        if (kb + 2 < NKB) load_stage((kb + 2) % NSTG, kb + 2);

        uint32_t aBase = aS[s] + rowA * PITCH_B + colA * 2;
        uint32_t bBase = bS[s] + rowB * PITCH_B + colB * 2;
        #pragma unroll
        for (int ks = 0; ks < 2; ks++) {
            uint32_t af[4][4];
            #pragma unroll
            for (int mt = 0; mt < 4; mt++)
                LDSM_X4(af[mt], aBase + mt * (16 * PITCH_B) + ks * 32);
            #pragma unroll
            for (int nh = 0; nh < 2; nh++) {
                uint32_t bf[2][4];
                #pragma unroll
                for (int n2 = 0; n2 < 2; n2++)
                    LDSM_X4(bf[n2], bBase + (nh * 32 + n2 * 16) * PITCH_B + ks * 32);
                #pragma unroll
                for (int mt = 0; mt < 4; mt++)
                    #pragma unroll
                    for (int nt = 0; nt < 4; nt++)
                        MMAF16(acc[mt][nh * 4 + nt], af[mt], &bf[nt >> 1][(nt & 1) * 2]);
            }
        }
    }

    __half* Srow = g_S + (size_t)b * LSEQ * LSEQ;
    const int ntile = (nBase >> 6) + warpN;
    #pragma unroll
    for (int mt = 0; mt < 4; mt++) {
        float vmax0 = -1e30f, vmax1 = -1e30f;
        #pragma unroll
        for (int j = 0; j < 8; j++) {
            int row = mBase + warpM * 64 + mt * 16 + g;
            int col = nBase + warpN * 64 + j * 8 + 2 * t;
            *(uint32_t*)(Srow + (size_t)(row    ) * LSEQ + col) = acc[mt][j][0];
            *(uint32_t*)(Srow + (size_t)(row + 8) * LSEQ + col) = acc[mt][j][1];
            __half2 v0 = *(__half2*)&acc[mt][j][0];
            __half2 v1 = *(__half2*)&acc[mt][j][1];
            vmax0 = fmaxf(vmax0, fmaxf(__low2float(v0), __high2float(v0)));
            vmax1 = fmaxf(vmax1, fmaxf(__low2float(v1), __high2float(v1)));
        }
        #pragma unroll
        for (int o = 1; o <= 2; o <<= 1) {
            vmax0 = fmaxf(vmax0, __shfl_xor_sync(0xffffffffu, vmax0, o));
            vmax1 = fmaxf(vmax1, __shfl_xor_sync(0xffffffffu, vmax1, o));
        }
        if (t == 0) {
            int row = mBase + warpM * 64 + mt * 16 + g;
            g_bmax[((size_t)b * LSEQ + row    ) * 32 + ntile] = __float2half(vmax0);
            g_bmax[((size_t)b * LSEQ + row + 8) * 32 + ntile] = __float2half(vmax1);
        }
    }
    __threadfence();
    __syncthreads();
    if (tid == 0) atomicAdd(&g_gemm_prog[b], 1);
}

// ---------------------------------------------------------------------------
#define CAP 64
#define MARGIN 1.0f

struct RefSm {
    int      cnt;
    float    thr;
    uint32_t flags;
    int      idx[CAP];
    float    dot[CAP];
    float    w[CAP];
};

__device__ __forceinline__ void refine_row(int b, int q, int tid,
                                           const float* __restrict__ Q,
                                           const float* __restrict__ Mem,
                                           float* __restrict__ Out, RefSm& rs) {
    const int lane = tid & 31, warp = tid >> 5;
    const __half* srow = g_S + ((size_t)b * LSEQ + q) * LSEQ;

    __syncthreads();                       // protect rs reuse across rows
    if (warp == 0) {
        float v = ldcg_half(&g_bmax[((size_t)b * LSEQ + q) * 32 + lane]);
        float mx = v;
        #pragma unroll
        for (int o = 16; o; o >>= 1) mx = fmaxf(mx, __shfl_xor_sync(0xffffffffu, mx, o));
        float thr = mx - MARGIN;
        uint32_t fl = __ballot_sync(0xffffffffu, v >= thr);
        if (lane == 0) { rs.thr = thr; rs.flags = fl; rs.cnt = 0; }
    }
    __syncthreads();

    {
        float thr = rs.thr;
        uint32_t flags = rs.flags;
        int nf = __popc(flags);
        int grp = tid >> 6;
        int t64 = tid & 63;
        for (int fi = grp; fi < nf; fi += 4) {
            int blk = __fns(flags, 0, fi + 1);
            int k = blk * 64 + t64;
            if (ldcg_half(&srow[k]) >= thr) {
                int p = atomicAdd(&rs.cnt, 1);
                if (p < CAP) rs.idx[p] = k;
            }
        }
    }
    __syncthreads();
    int nc = min(rs.cnt, CAP);

    if (nc == 1) {
        const float4* src = (const float4*)(Mem + ((size_t)b * LSEQ + rs.idx[0]) * DDIM);
        float4* dst = (float4*)(Out + ((size_t)b * LSEQ + q) * DDIM);
        dst[tid] = src[tid];
        return;                            // uniform across CTA
    }

    if (tid == 0) {
        for (int i = 1; i < nc; i++) {
            int v = rs.idx[i], j = i - 1;
            while (j >= 0 && rs.idx[j] > v) { rs.idx[j + 1] = rs.idx[j]; j--; }
            rs.idx[j + 1] = v;
        }
    }
    __syncthreads();

    const float* qrow = Q + ((size_t)b * LSEQ + q) * DDIM;
    for (int j = warp; j < nc; j += 8) {
        const float* mrow = Mem + ((size_t)b * LSEQ + rs.idx[j]) * DDIM;
        float p = 0.f;
        #pragma unroll 4
        for (int d = lane; d < DDIM; d += 32) p += qrow[d] * mrow[d];
        #pragma unroll
        for (int o = 16; o; o >>= 1) p += __shfl_xor_sync(0xffffffffu, p, o);
        if (lane == 0) rs.dot[j] = p;
    }
    __syncthreads();

    if (tid == 0) {
        float dm = -1e30f;
        for (int j = 0; j < nc; j++) dm = fmaxf(dm, rs.dot[j]);
        float sum = 0.f;
        for (int j = 0; j < nc; j++) {
            float w = expf((rs.dot[j] - dm) * TAW_INV);
            rs.w[j] = w; sum += w;
        }
        float inv = 1.0f / sum;
        for (int j = 0; j < nc; j++) rs.w[j] *= inv;
    }
    __syncthreads();

    const float4* M4 = (const float4*)Mem;
    float4* dst = (float4*)(Out + ((size_t)b * LSEQ + q) * DDIM);
    float4 a = make_float4(0.f, 0.f, 0.f, 0.f);
    for (int j = 0; j < nc; j++) {
        float w = rs.w[j];
        float4 v = M4[(((size_t)b * LSEQ + rs.idx[j]) * DDIM >> 2) + tid];
        a.x += w * v.x; a.y += w * v.y; a.z += w * v.z; a.w += w * v.w;
    }
    dst[tid] = a;
}

// ---------------------------------------------------------------------------
// Init + fused persistent kernel
// ---------------------------------------------------------------------------
__global__ void init_kernel() {
    int i = threadIdx.x;
    if (i == 0) g_ticket = 0;
    if (i < BATCH) { g_conv_prog[i] = 0; g_gemm_prog[i] = 0; }
}

__global__ __launch_bounds__(256, 2) void fused_kernel(const float* __restrict__ q,
                                                       const float* __restrict__ m,
                                                       float* __restrict__ out) {
    extern __shared__ __align__(16) char dsm[];
    __shared__ int s_t;
    __shared__ RefSm rs;
    const int tid = threadIdx.x;

    for (;;) {
        __syncthreads();
        if (tid == 0) s_t = atomicAdd(&g_ticket, 1);
        __syncthreads();
        int t = s_t;
        if (t >= NTICK) return;            // uniform exit

        if (t < NCG) {
            int seg = t % SEG;
            if (seg < CONV_PER_B) {
                conv_ticket(t, q, m, tid);
            } else {
                int b = t / SEG;
                gemm_ticket(b, seg - CONV_PER_B, dsm, tid);
            }
        } else {
            int rt = t - NCG;
            int b = rt / REF_PER_B;
            int q0 = (rt % REF_PER_B) * 32;
            cta_wait(&g_gemm_prog[b], GEMM_PER_B, tid);
            for (int qq = q0; qq < q0 + 32; qq++)
                refine_row(b, qq, tid, q, m, out, rs);
        }
    }
}

// ---------------------------------------------------------------------------
extern "C" void kernel_launch(void* const* d_in, const int* in_sizes, int n_in,
                              void* d_out, int out_size) {
    const float* q = (const float*)d_in[0];
    const float* m = (const float*)d_in[1];
    float* out = (float*)d_out;

    // Host-side attribute set (not a stream op -> capture-safe)
    cudaFuncSetAttribute(fused_kernel,
                         cudaFuncAttributeMaxDynamicSharedMemorySize, QK_DSMEM);

    init_kernel<<<1, 32>>>();
    fused_kernel<<<NCTA, 256, QK_DSMEM>>>(q, m, out);
}

// round 15
// speedup vs baseline: 1.4466x; 1.3208x over previous
#include <cuda_runtime.h>
#include <cuda_fp16.h>
#include <cstdint>

// Problem shape (fixed by the dataset)
#define BATCH 8
#define LSEQ  2048
#define DDIM  1024
#define TAW_INV 50.0f

// Scratch (static __device__ arrays — allocation-free rule)
__device__ __half g_Qh[(size_t)BATCH * LSEQ * DDIM];          // 33.5 MB
__device__ __half g_Mh[(size_t)BATCH * LSEQ * DDIM];          // 33.5 MB
__device__ __half g_S [(size_t)BATCH * LSEQ * LSEQ];          // 67 MB (approx dots)
__device__ __half g_bmax[(size_t)BATCH * LSEQ * 32];          // per-row 64-col block max

// Scheduling state (reset by init_kernel every invocation)
__device__ int g_ticket;
__device__ int g_conv_prog[BATCH];

// Ticket layout: per batch b: 512 conv tickets then 128 gemm tickets.
#define CONV_PER_B 512
#define GEMM_PER_B 128
#define SEG        (CONV_PER_B + GEMM_PER_B)      // 640
#define NTICK      (BATCH * SEG)                  // 5120
#define NCTA       296

// ---------------------------------------------------------------------------
// Helpers
// ---------------------------------------------------------------------------
__device__ __forceinline__ uint32_t smem_u32(const void* p) {
    uint32_t a;
    asm("{ .reg .u64 t; cvta.to.shared.u64 t, %1; cvt.u32.u64 %0, t; }"
        : "=r"(a) : "l"(p));
    return a;
}

__device__ __forceinline__ void cp_async16(uint32_t saddr, const void* gptr) {
    asm volatile("cp.async.cg.shared.global [%0], [%1], 16;\n" :: "r"(saddr), "l"(gptr));
}

#define LDSM_X4(r, addr) \
    asm volatile("ldmatrix.sync.aligned.m8n8.x4.shared.b16 {%0,%1,%2,%3}, [%4];" \
        : "=r"((r)[0]), "=r"((r)[1]), "=r"((r)[2]), "=r"((r)[3]) : "r"(addr))

#define MMAF16(d, a, b)                                                       \
    asm volatile(                                                             \
        "mma.sync.aligned.m16n8k16.row.col.f16.f16.f16.f16 "                  \
        "{%0,%1}, {%2,%3,%4,%5}, {%6,%7}, {%0,%1};\n"                         \
        : "+r"((d)[0]), "+r"((d)[1])                                          \
        : "r"((a)[0]), "r"((a)[1]), "r"((a)[2]), "r"((a)[3]),                 \
          "r"((b)[0]), "r"((b)[1]))

// bounded acquire-spin on a progress counter (construct proven in R12 run;
// bounded so a logic bug yields rel_err, never a container hang)
__device__ __forceinline__ void cta_wait(int* ctr, int target, int tid) {
    if (tid == 0) {
        int it = 0;
        while (atomicAdd(ctr, 0) < target && ++it < (1 << 22)) {}
    }
    __syncthreads();
}

// ---------------------------------------------------------------------------
// GEMM config (identical to validated R10 kernel)
// ---------------------------------------------------------------------------
#define BM 128
#define BN 256
#define BK 32
#define PITCH_B 80
#define A_STG (BM * PITCH_B)               // 10240
#define B_STG (BN * PITCH_B)               // 20480
#define NSTG 3
#define NKB (DDIM / BK)                    // 32
#define QK_DSMEM (NSTG * (A_STG + B_STG))  // 92160 B

// ---------------------------------------------------------------------------
// Phase bodies (conv + gemm only — refine is a separate kernel, so the fused
// function's register allocation stays at the GEMM's own level)
// ---------------------------------------------------------------------------
__device__ __forceinline__ void conv_ticket(int b, int seg, const float* __restrict__ q,
                                            const float* __restrict__ m, int tid) {
    size_t base = (size_t)b * (LSEQ * DDIM / 4) + (size_t)seg * 1024;
    const float4* q4 = (const float4*)q;
    const float4* m4 = (const float4*)m;
    __half2* Q2 = (__half2*)g_Qh;
    __half2* M2 = (__half2*)g_Mh;
    #pragma unroll
    for (int k = 0; k < 4; k++) {
        size_t i = base + tid + k * 256;
        float4 vq = q4[i];
        float4 vm = m4[i];
        Q2[2*i]   = __floats2half2_rn(vq.x, vq.y);
        Q2[2*i+1] = __floats2half2_rn(vq.z, vq.w);
        M2[2*i]   = __floats2half2_rn(vm.x, vm.y);
        M2[2*i+1] = __floats2half2_rn(vm.z, vm.w);
    }
    __threadfence();
    __syncthreads();
    if (tid == 0) atomicAdd(&g_conv_prog[b], 1);
}

__device__ __forceinline__ void gemm_ticket(int b, int tb, char* dsm, int tid) {
    cta_wait(&g_conv_prog[b], CONV_PER_B, tid);

    const uint32_t sb = smem_u32(dsm);
    const int lane  = tid & 31;
    const int warp  = tid >> 5;
    const int warpM = warp & 1;
    const int warpN = warp >> 1;
    const int g     = lane >> 2;
    const int t     = lane & 3;

    const int mBase = (tb >> 3) * BM;      // 16 m-tiles
    const int nBase = (tb & 7) * BN;       // 8 n-tiles
    const __half* Qb = g_Qh + (size_t)b * LSEQ * DDIM;
    const __half* Mb = g_Mh + (size_t)b * LSEQ * DDIM;

    uint32_t aS[NSTG], bS[NSTG];
    #pragma unroll
    for (int s = 0; s < NSTG; s++) {
        aS[s] = sb + s * (A_STG + B_STG);
        bS[s] = aS[s] + A_STG;
    }

    const int rowA = warpM * 64 + (lane & 7) + ((lane >> 3) & 1) * 8;
    const int colA = ((lane >> 4) & 1) * 8;
    const int rowB = warpN * 64 + (lane & 7) + ((lane >> 4) & 1) * 8;
    const int colB = ((lane >> 3) & 1) * 8;

    uint32_t acc[4][8][2];
    #pragma unroll
    for (int i = 0; i < 4; i++)
        #pragma unroll
        for (int j = 0; j < 8; j++) { acc[i][j][0] = 0u; acc[i][j][1] = 0u; }

    auto load_stage = [&](int s, int kb) {
        int k0 = kb * BK;
        #pragma unroll
        for (int i = 0; i < 2; i++) {
            int j = tid + i * 256;
            int row = j >> 2;
            int c16 = (j & 3) * 16;
            cp_async16(aS[s] + row * PITCH_B + c16,
                       Qb + (size_t)(mBase + row) * DDIM + k0 + c16 / 2);
        }
        #pragma unroll
        for (int i = 0; i < 4; i++) {
            int j = tid + i * 256;
            int row = j >> 2;
            int c16 = (j & 3) * 16;
            cp_async16(bS[s] + row * PITCH_B + c16,
                       Mb + (size_t)(nBase + row) * DDIM + k0 + c16 / 2);
        }
        asm volatile("cp.async.commit_group;\n");
    };

    load_stage(0, 0);
    load_stage(1, 1);

    for (int kb = 0; kb < NKB; kb++) {
        int s = kb % NSTG;
        if (kb + 2 < NKB) asm volatile("cp.async.wait_group 1;\n");
        else              asm volatile("cp.async.wait_group 0;\n");
        __syncthreads();

        if (kb + 2 < NKB) load_stage((kb + 2) % NSTG, kb + 2);

        uint32_t aBase = aS[s] + rowA * PITCH_B + colA * 2;
        uint32_t bBase = bS[s] + rowB * PITCH_B + colB * 2;
        #pragma unroll
        for (int ks = 0; ks < 2; ks++) {
            uint32_t af[4][4];
            #pragma unroll
            for (int mt = 0; mt < 4; mt++)
                LDSM_X4(af[mt], aBase + mt * (16 * PITCH_B) + ks * 32);
            #pragma unroll
            for (int nh = 0; nh < 2; nh++) {
                uint32_t bf[2][4];
                #pragma unroll
                for (int n2 = 0; n2 < 2; n2++)
                    LDSM_X4(bf[n2], bBase + (nh * 32 + n2 * 16) * PITCH_B + ks * 32);
                #pragma unroll
                for (int mt = 0; mt < 4; mt++)
                    #pragma unroll
                    for (int nt = 0; nt < 4; nt++)
                        MMAF16(acc[mt][nh * 4 + nt], af[mt], &bf[nt >> 1][(nt & 1) * 2]);
            }
        }
    }

    __half* Srow = g_S + (size_t)b * LSEQ * LSEQ;
    const int ntile = (nBase >> 6) + warpN;
    #pragma unroll
    for (int mt = 0; mt < 4; mt++) {
        float vmax0 = -1e30f, vmax1 = -1e30f;
        #pragma unroll
        for (int j = 0; j < 8; j++) {
            int row = mBase + warpM * 64 + mt * 16 + g;
            int col = nBase + warpN * 64 + j * 8 + 2 * t;
            *(uint32_t*)(Srow + (size_t)(row    ) * LSEQ + col) = acc[mt][j][0];
            *(uint32_t*)(Srow + (size_t)(row + 8) * LSEQ + col) = acc[mt][j][1];
            __half2 v0 = *(__half2*)&acc[mt][j][0];
            __half2 v1 = *(__half2*)&acc[mt][j][1];
            vmax0 = fmaxf(vmax0, fmaxf(__low2float(v0), __high2float(v0)));
            vmax1 = fmaxf(vmax1, fmaxf(__low2float(v1), __high2float(v1)));
        }
        #pragma unroll
        for (int o = 1; o <= 2; o <<= 1) {
            vmax0 = fmaxf(vmax0, __shfl_xor_sync(0xffffffffu, vmax0, o));
            vmax1 = fmaxf(vmax1, __shfl_xor_sync(0xffffffffu, vmax1, o));
        }
        if (t == 0) {
            int row = mBase + warpM * 64 + mt * 16 + g;
            g_bmax[((size_t)b * LSEQ + row    ) * 32 + ntile] = __float2half(vmax0);
            g_bmax[((size_t)b * LSEQ + row + 8) * 32 + ntile] = __float2half(vmax1);
        }
    }
}

// ---------------------------------------------------------------------------
// Init + fused conv+gemm persistent kernel
// ---------------------------------------------------------------------------
__global__ void init_kernel() {
    int i = threadIdx.x;
    if (i == 0) g_ticket = 0;
    if (i < BATCH) g_conv_prog[i] = 0;
}

__global__ __launch_bounds__(256, 2) void fused_cg_kernel(const float* __restrict__ q,
                                                          const float* __restrict__ m) {
    extern __shared__ __align__(16) char dsm[];
    __shared__ int s_t;
    const int tid = threadIdx.x;

    for (;;) {
        __syncthreads();
        if (tid == 0) s_t = atomicAdd(&g_ticket, 1);
        __syncthreads();
        int t = s_t;
        if (t >= NTICK) return;            // uniform exit

        int b = t / SEG, seg = t % SEG;
        if (seg < CONV_PER_B) conv_ticket(b, seg, q, m, tid);
        else                  gemm_ticket(b, seg - CONV_PER_B, dsm, tid);
    }
}

// ---------------------------------------------------------------------------
// Refine kernel (separate — identical to validated R10 version)
// ---------------------------------------------------------------------------
#define CAP 64
#define MARGIN 1.0f

__global__ __launch_bounds__(256) void refine_kernel(const float* __restrict__ Q,
                                                     const float* __restrict__ Mem,
                                                     float* __restrict__ Out) {
    const int b = blockIdx.y, q = blockIdx.x, tid = threadIdx.x;
    const int lane = tid & 31, warp = tid >> 5;
    const __half* srow = g_S + ((size_t)b * LSEQ + q) * LSEQ;

    __shared__ int      s_cnt;
    __shared__ float    s_thr;
    __shared__ uint32_t s_flags;
    __shared__ int      s_idx[CAP];
    __shared__ float    s_dot[CAP];
    __shared__ float    s_w[CAP];

    // 1) block maxes -> row max, threshold, flagged blocks (warp 0)
    if (warp == 0) {
        float v = __half2float(g_bmax[((size_t)b * LSEQ + q) * 32 + lane]);
        float mx = v;
        #pragma unroll
        for (int o = 16; o; o >>= 1) mx = fmaxf(mx, __shfl_xor_sync(0xffffffffu, mx, o));
        float thr = mx - MARGIN;
        uint32_t fl = __ballot_sync(0xffffffffu, v >= thr);
        if (lane == 0) { s_thr = thr; s_flags = fl; s_cnt = 0; }
    }
    __syncthreads();

    // 2) candidate scan over flagged 64-score blocks only
    {
        float thr = s_thr;
        uint32_t flags = s_flags;
        int nf = __popc(flags);
        int grp = tid >> 6;                  // 4 groups of 64 threads
        int t64 = tid & 63;
        for (int fi = grp; fi < nf; fi += 4) {
            int blk = __fns(flags, 0, fi + 1);
            int k = blk * 64 + t64;
            if (__half2float(srow[k]) >= thr) {
                int p = atomicAdd(&s_cnt, 1);
                if (p < CAP) s_idx[p] = k;
            }
        }
    }
    __syncthreads();
    int nc = min(s_cnt, CAP);

    // 3) fast path: single candidate -> output = that memory row exactly
    if (nc == 1) {
        const float4* src = (const float4*)(Mem + ((size_t)b * LSEQ + s_idx[0]) * DDIM);
        float4* dst = (float4*)(Out + ((size_t)b * LSEQ + q) * DDIM);
        dst[tid] = src[tid];                 // 256 threads x float4 = 1024
        return;
    }

    if (tid == 0) {                          // sort for determinism
        for (int i = 1; i < nc; i++) {
            int v = s_idx[i], j = i - 1;
            while (j >= 0 && s_idx[j] > v) { s_idx[j + 1] = s_idx[j]; j--; }
            s_idx[j + 1] = v;
        }
    }
    __syncthreads();

    // 4) exact fp32 dots, one warp per candidate
    const float* qrow = Q + ((size_t)b * LSEQ + q) * DDIM;
    for (int j = warp; j < nc; j += 8) {
        const float* mrow = Mem + ((size_t)b * LSEQ + s_idx[j]) * DDIM;
        float p = 0.f;
        #pragma unroll 4
        for (int d = lane; d < DDIM; d += 32) p += qrow[d] * mrow[d];
        #pragma unroll
        for (int o = 16; o; o >>= 1) p += __shfl_xor_sync(0xffffffffu, p, o);
        if (lane == 0) s_dot[j] = p;
    }
    __syncthreads();

    // 5) exact softmax over candidates
    if (tid == 0) {
        float dm = -1e30f;
        for (int j = 0; j < nc; j++) dm = fmaxf(dm, s_dot[j]);
        float sum = 0.f;
        for (int j = 0; j < nc; j++) {
            float w = expf((s_dot[j] - dm) * TAW_INV);
            s_w[j] = w; sum += w;
        }
        float inv = 1.0f / sum;
        for (int j = 0; j < nc; j++) s_w[j] *= inv;
    }
    __syncthreads();

    // 6) output mixture (float4 vectorized)
    const float4* M4 = (const float4*)Mem;
    float4* dst = (float4*)(Out + ((size_t)b * LSEQ + q) * DDIM);
    float4 a = make_float4(0.f, 0.f, 0.f, 0.f);
    for (int j = 0; j < nc; j++) {
        float w = s_w[j];
        float4 v = M4[(((size_t)b * LSEQ + s_idx[j]) * DDIM >> 2) + tid];
        a.x += w * v.x; a.y += w * v.y; a.z += w * v.z; a.w += w * v.w;
    }
    dst[tid] = a;
}

// ---------------------------------------------------------------------------
extern "C" void kernel_launch(void* const* d_in, const int* in_sizes, int n_in,
                              void* d_out, int out_size) {
    const float* q = (const float*)d_in[0];
    const float* m = (const float*)d_in[1];
    float* out = (float*)d_out;

    // Host-side attribute set (not a stream op -> capture-safe)
    cudaFuncSetAttribute(fused_cg_kernel,
                         cudaFuncAttributeMaxDynamicSharedMemorySize, QK_DSMEM);

    init_kernel<<<1, 32>>>();
    fused_cg_kernel<<<NCTA, 256, QK_DSMEM>>>(q, m);

    dim3 rg(LSEQ, BATCH);
    refine_kernel<<<rg, 256>>>(q, m, out);
}